// round 15
// baseline (speedup 1.0000x reference)
#include <cuda_runtime.h>
#include <cuda_fp16.h>
#include <cstdint>

// ---------------------------------------------------------------------------
// DeBiLevelRoutingAttention block. Round 15: k1 3-stage pipeline + 3 CTAs/SM
// (launch_bounds(128,3)) for 12 warps/SM of latency hiding; warp tile 64x64
// (128B LDSM per HMMA) retained from R14.
// ---------------------------------------------------------------------------

#define N_IMG  16
#define C_DIM  512
#define H_IMG  56
#define W_IMG  56
#define HW     3136
#define CHW    (C_DIM * HW)
#define QKC    512
#define NWIN   7
#define P2     49
#define W2     64
#define TOPK   4
#define HEADS  8
#define HD     64
#define SCALE  0.04419417382415922f   // 512^-0.5

// ----------------------------- scratch ------------------------------------
__device__ float g_qwin[(size_t)N_IMG * P2 * C_DIM];
__device__ float g_kwin[(size_t)N_IMG * P2 * C_DIM];
__device__ int   g_idx [N_IMG * P2 * TOPK];
__device__ __align__(16) __half g_xh [(size_t)N_IMG * CHW];
__device__ __align__(16) __half g_wh [1536 * 512];
__device__ __align__(16) __half g_qh [(size_t)N_IMG * P2 * W2 * 512];   // pre-scaled
__device__ __align__(16) __half g_kvh[(size_t)N_IMG * P2 * W2 * 1024];
__device__ __align__(16) __half g_aoh[(size_t)N_IMG * P2 * W2 * 512];

// ----------------------------- helpers ------------------------------------
__device__ __forceinline__ uint32_t pack2(float lo, float hi) {
    __half2 h = __floats2half2_rn(lo, hi);
    return *reinterpret_cast<uint32_t*>(&h);
}
__device__ __forceinline__ uint32_t smem_u32(const void* p) {
    return (uint32_t)__cvta_generic_to_shared(p);
}
__device__ __forceinline__ void mma_f16(float c[4], const uint32_t a[4],
                                        uint32_t b0, uint32_t b1) {
    asm volatile(
        "mma.sync.aligned.m16n8k16.row.col.f32.f16.f16.f32 "
        "{%0,%1,%2,%3}, {%4,%5,%6,%7}, {%8,%9}, {%0,%1,%2,%3};"
        : "+f"(c[0]), "+f"(c[1]), "+f"(c[2]), "+f"(c[3])
        : "r"(a[0]), "r"(a[1]), "r"(a[2]), "r"(a[3]), "r"(b0), "r"(b1));
}
#define CP_ASYNC16(dst, src) \
    asm volatile("cp.async.cg.shared.global [%0], [%1], 16;" \
                 :: "r"(dst), "l"(src) : "memory")
#define CP_COMMIT() asm volatile("cp.async.commit_group;" ::: "memory")
#define CP_WAIT(n)  asm volatile("cp.async.wait_group %0;" :: "n"(n) : "memory")
#define LDSM_X4(r, a) \
    asm volatile("ldmatrix.sync.aligned.m8n8.x4.shared.b16 {%0,%1,%2,%3}, [%4];" \
        : "=r"((r)[0]), "=r"((r)[1]), "=r"((r)[2]), "=r"((r)[3]) : "r"(a))
#define LDSM_X4T(r, a) \
    asm volatile("ldmatrix.sync.aligned.m8n8.x4.trans.shared.b16 {%0,%1,%2,%3}, [%4];" \
        : "=r"((r)[0]), "=r"((r)[1]), "=r"((r)[2]), "=r"((r)[3]) : "r"(a))

// ===========================================================================
// Dummy no-op kernel: keeps ncu's captured launch on k1.
// ===========================================================================
__global__ void kd_nop() {}

// ===========================================================================
// Kernel 0: convert x and w_qkv to fp16.
// ===========================================================================
__global__ __launch_bounds__(256) void k0_half(const float* __restrict__ x,
                                               const float* __restrict__ w) {
    const int i = blockIdx.x * 256 + threadIdx.x;
    const int NX4 = (N_IMG * CHW) >> 2;
    const int NW4 = (1536 * 512) >> 2;
    if (i < NX4) {
        float4 v = ((const float4*)x)[i];
        uint32_t* d = (uint32_t*)g_xh;
        d[2 * i]     = pack2(v.x, v.y);
        d[2 * i + 1] = pack2(v.z, v.w);
    }
    if (i < NW4) {
        float4 v = ((const float4*)w)[i];
        uint32_t* d = (uint32_t*)g_wh;
        d[2 * i]     = pack2(v.x, v.y);
        d[2 * i + 1] = pack2(v.z, v.w);
    }
}

// ===========================================================================
// Kernel 1: QKV GEMM, fp16 mma. Block 128x128, 4 warps (2Mx2N), warp 64x64.
// K-chunk 32, 3-stage cp.async, 3 CTAs/SM. A smem [k][m] pitch 272B;
// B smem [n][k] pitch 80B. Per k16 step: 8 LDSM / 32 HMMA.
// ===========================================================================
#define K1_ABYTES 8704                 // 32 * 272
#define K1_BBYTES 10240                // 128 * 80
#define K1_STAGE  (K1_ABYTES + K1_BBYTES)
#define K1_SMEM   (3 * K1_STAGE)       // 56832

__global__ __launch_bounds__(128, 3) void k1_qkv_tc(const float* __restrict__ bqkv) {
    extern __shared__ char smc[];
    const uint32_t sb = smem_u32(smc);
    const int t  = threadIdx.x;
    const int o0 = blockIdx.x * 128;
    const int m0 = blockIdx.y * 128;

    const int wid = t >> 5, lane = t & 31;
    const int mw = (wid & 1) * 64;
    const int nw = (wid >> 1) * 64;
    const int grp = lane >> 3, li = lane & 7;
    const int a_k = li + ((grp & 2) ? 8 : 0);
    const int a_m = (grp & 1) ? 8 : 0;
    const int b_n = li + ((grp & 2) ? 8 : 0);
    const int b_k = (grp & 1) ? 8 : 0;
    const int lr = lane >> 2, lq = lane & 3;

    // A loader: 4 iters x 128 thr cover 32 k-rows x 128 m (8-pixel chunks).
    const int a_mh = (t & 15) * 8;
    const int mA   = m0 + a_mh;
    const int nA   = mA / HW;
    const int hwA  = mA - nA * HW;
    const __half* axp = g_xh + (size_t)nA * CHW + hwA;
    const int a_kr0 = t >> 4;            // + 8*i
    // B loader: 4 iters x 128 thr cover 128 n-rows x 32 k.
    const int b_bn0 = t >> 2;            // + 32*i
    const int b_bh  = (t & 3) * 8;

    float c[4][8][4];
#pragma unroll
    for (int mt = 0; mt < 4; mt++)
#pragma unroll
        for (int nt = 0; nt < 8; nt++)
#pragma unroll
            for (int i = 0; i < 4; i++) c[mt][nt][i] = 0.f;

#define K1_ISSUE(kc_) do {                                                    \
    const int s_ = (kc_) % 3;                                                 \
    const uint32_t ab_ = sb + s_ * K1_STAGE;                                  \
    const uint32_t bb_ = ab_ + K1_ABYTES;                                     \
    _Pragma("unroll")                                                         \
    for (int i_ = 0; i_ < 4; i_++) {                                          \
        const int kr_ = a_kr0 + 8 * i_;                                       \
        CP_ASYNC16(ab_ + kr_ * 272 + a_mh * 2,                                \
                   axp + (size_t)((kc_) * 32 + kr_) * HW);                    \
        const int bn_ = b_bn0 + 32 * i_;                                      \
        CP_ASYNC16(bb_ + bn_ * 80 + b_bh * 2,                                 \
                   g_wh + (size_t)(o0 + bn_) * 512 + (kc_) * 32 + b_bh);      \
    }                                                                         \
} while (0)

    K1_ISSUE(0); CP_COMMIT();
    K1_ISSUE(1); CP_COMMIT();

    for (int kc = 0; kc < 16; kc++) {
        CP_WAIT(1);
        __syncthreads();
        if (kc + 2 < 16) { K1_ISSUE(kc + 2); }
        CP_COMMIT();
        const uint32_t ab = sb + (kc % 3) * K1_STAGE;
        const uint32_t bb = ab + K1_ABYTES;
#pragma unroll
        for (int ks = 0; ks < 2; ks++) {
            uint32_t a[4][4];
#pragma unroll
            for (int mt = 0; mt < 4; mt++)
                LDSM_X4T(a[mt], ab + (ks * 16 + a_k) * 272 + (mw + mt * 16 + a_m) * 2);
            uint32_t b[4][4];
#pragma unroll
            for (int ntp = 0; ntp < 4; ntp++)
                LDSM_X4(b[ntp], bb + (nw + ntp * 16 + b_n) * 80 + (ks * 16 + b_k) * 2);
#pragma unroll
            for (int mt = 0; mt < 4; mt++)
#pragma unroll
                for (int ntp = 0; ntp < 4; ntp++) {
                    mma_f16(c[mt][2 * ntp],     a[mt], b[ntp][0], b[ntp][1]);
                    mma_f16(c[mt][2 * ntp + 1], a[mt], b[ntp][2], b[ntp][3]);
                }
        }
    }

    const bool isq = (o0 < QKC);
#pragma unroll
    for (int mt = 0; mt < 4; mt++) {
#pragma unroll
        for (int half = 0; half < 2; half++) {
            const int row = mw + mt * 16 + lr + half * 8;
            const int m   = m0 + row;
            const int n   = m / HW;
            const int hw  = m - n * HW;
            const int h   = hw / W_IMG;
            const int wp  = hw - h * W_IMG;
            const int p   = (h >> 3) * NWIN + (wp >> 3);
            const int pix = ((h & 7) << 3) + (wp & 7);
            const size_t npix = (size_t)((n * P2 + p) * W2 + pix);
            uint32_t* dsth = isq ? ((uint32_t*)g_qh  + npix * 256 + (o0 >> 1))
                                 : ((uint32_t*)g_kvh + npix * 512 + ((o0 - QKC) >> 1));
#pragma unroll
            for (int nt = 0; nt < 8; nt++) {
                const int col = nw + nt * 8 + lq * 2;
                float vx = c[mt][nt][half * 2 + 0] + bqkv[o0 + col];
                float vy = c[mt][nt][half * 2 + 1] + bqkv[o0 + col + 1];
                dsth[col >> 1] = isq ? pack2(vx * SCALE, vy * SCALE) : pack2(vx, vy);
            }
        }
    }
#undef K1_ISSUE
}

// ===========================================================================
// Kernel 2: window means from fp16 q/kv, fp32 accumulation.
// ===========================================================================
__global__ __launch_bounds__(256) void k2_mean() {
    const int np = blockIdx.x;
    const int c2 = threadIdx.x;
    const uint32_t* qb = (const uint32_t*)g_qh  + (size_t)np * W2 * 256 + c2;
    const uint32_t* kb = (const uint32_t*)g_kvh + (size_t)np * W2 * 512 + c2;
    float sqx = 0.f, sqy = 0.f, skx = 0.f, sky = 0.f;
#pragma unroll 8
    for (int pix = 0; pix < W2; pix++) {
        uint32_t qv = qb[(size_t)pix * 256];
        uint32_t kv = kb[(size_t)pix * 512];
        float2 qf = __half22float2(*reinterpret_cast<__half2*>(&qv));
        float2 kf = __half22float2(*reinterpret_cast<__half2*>(&kv));
        sqx += qf.x; sqy += qf.y;
        skx += kf.x; sky += kf.y;
    }
    *(float2*)(g_qwin + (size_t)np * 512 + 2 * c2) = make_float2(sqx * (1.f/64.f), sqy * (1.f/64.f));
    *(float2*)(g_kwin + (size_t)np * 512 + 2 * c2) = make_float2(skx * (1.f/64.f), sky * (1.f/64.f));
}

// ===========================================================================
// Kernel 3: routing logits + top-4 (warp-parallel argmax). grid 784 x 128.
// ===========================================================================
__global__ __launch_bounds__(128) void k3_route() {
    __shared__ float qs[512];
    __shared__ float lg[P2];
    const int np = blockIdx.x;
    const int n  = np / P2;
    const int t  = threadIdx.x;
    for (int c = t; c < 512; c += 128)
        qs[c] = g_qwin[(size_t)np * 512 + c];
    __syncthreads();
    {
        const int win = (t >> 1) < P2 ? (t >> 1) : (P2 - 1);
        const int hf  = t & 1;
        const float4* kr = (const float4*)(g_kwin + (size_t)(n * P2 + win) * 512) + hf * 64;
        const float*  qh = qs + hf * 256;
        float s = 0.f;
#pragma unroll 8
        for (int c4 = 0; c4 < 64; c4++) {
            float4 k4 = kr[c4];
            s += qh[c4 * 4 + 0] * k4.x + qh[c4 * 4 + 1] * k4.y +
                 qh[c4 * 4 + 2] * k4.z + qh[c4 * 4 + 3] * k4.w;
        }
        s += __shfl_xor_sync(0xffffffffu, s, 1);
        if (hf == 0 && (t >> 1) < P2) lg[win] = s;
    }
    __syncthreads();
    if (t < 32) {
        float v0 = (t < P2)      ? lg[t]      : -1e30f;
        float v1 = (t + 32 < P2) ? lg[t + 32] : -1e30f;
#pragma unroll
        for (int sel = 0; sel < TOPK; sel++) {
            float m; int idx;
            if (v0 >= v1) { m = v0; idx = t; } else { m = v1; idx = t + 32; }
#pragma unroll
            for (int off = 16; off; off >>= 1) {
                float om = __shfl_xor_sync(0xffffffffu, m, off);
                int   oi = __shfl_xor_sync(0xffffffffu, idx, off);
                if (om > m || (om == m && oi < idx)) { m = om; idx = oi; }
            }
            if (t == 0) g_idx[np * TOPK + sel] = idx;
            const int wsel = __shfl_sync(0xffffffffu, idx, 0);
            if (wsel == t)      v0 = -1e30f;
            if (wsel == t + 32) v1 = -1e30f;
        }
    }
}

// ===========================================================================
// Kernel 4: attention, fp16 mma + double-buffered cp.async KV (unchanged).
// ===========================================================================
#define K4_TILE 9216                   // 64 * 144
#define K4_SMEM (5 * K4_TILE)

__global__ __launch_bounds__(128) void k4_attn_tc() {
    extern __shared__ char smc[];
    const uint32_t sb = smem_u32(smc);
    const uint32_t Qb = sb;

    const int head = blockIdx.x;
    const int np   = blockIdx.y;
    const int n    = np / P2;
    const int t    = threadIdx.x;
    const int wid  = t >> 5;
    const int lane = t & 31;
    const int mw   = wid * 16;
    const int lr   = lane >> 2;
    const int lq   = lane & 3;
    const int grp  = lane >> 3, li = lane & 7;

    const int q_r   = mw + li + ((grp & 1) ? 8 : 0);
    const int q_k   = (grp & 2) ? 8 : 0;
    const int k_n   = li + ((grp & 2) ? 8 : 0);
    const int k_k   = (grp & 1) ? 8 : 0;
    const int v_key = li + ((grp & 1) ? 8 : 0);
    const int v_d   = (grp & 2) ? 8 : 0;

    int widx[TOPK];
#pragma unroll
    for (int i = 0; i < TOPK; i++) widx[i] = g_idx[np * TOPK + i];

#define K4_KV_ISSUE(ts_) do {                                                   \
    const int s_ = (ts_) & 1;                                                   \
    const uint32_t Kb_ = sb + (1 + 2 * s_) * K4_TILE;                           \
    const uint32_t Vb_ = Kb_ + K4_TILE;                                         \
    const __half* kvsrc_ = g_kvh + (size_t)(n * P2 + widx[ts_]) * 64 * 1024 + head * HD; \
    _Pragma("unroll")                                                           \
    for (int i_ = 0; i_ < 4; i_++) {                                            \
        int cq_ = i_ * 128 + t;                                                 \
        int pix_ = cq_ >> 3, h8_ = (cq_ & 7) * 8;                               \
        CP_ASYNC16(Kb_ + pix_ * 144 + h8_ * 2, kvsrc_ + (size_t)pix_ * 1024 + h8_);       \
        CP_ASYNC16(Vb_ + pix_ * 144 + h8_ * 2, kvsrc_ + (size_t)pix_ * 1024 + 512 + h8_); \
    }                                                                           \
} while (0)

    {
        const __half* qsrc = g_qh + (size_t)np * 64 * 512 + head * HD;
#pragma unroll
        for (int i = 0; i < 4; i++) {
            int cq = i * 128 + t;
            int pix = cq >> 3, h8 = (cq & 7) * 8;
            CP_ASYNC16(Qb + pix * 144 + h8 * 2, qsrc + (size_t)pix * 512 + h8);
        }
        K4_KV_ISSUE(0);
        CP_COMMIT();
        K4_KV_ISSUE(1);
        CP_COMMIT();
    }

    float Of[8][4];
#pragma unroll
    for (int dt = 0; dt < 8; dt++)
#pragma unroll
        for (int i = 0; i < 4; i++) Of[dt][i] = 0.f;
    float mrun0 = -1e30f, mrun1 = -1e30f, lrun0 = 0.f, lrun1 = 0.f;

    for (int tsel = 0; tsel < TOPK; tsel++) {
        CP_WAIT(1);
        __syncthreads();
        const uint32_t Kb = sb + (1 + 2 * (tsel & 1)) * K4_TILE;
        const uint32_t Vb = Kb + K4_TILE;

        float sf[8][4];
#pragma unroll
        for (int nt = 0; nt < 8; nt++)
#pragma unroll
            for (int i = 0; i < 4; i++) sf[nt][i] = 0.f;
#pragma unroll
        for (int ks = 0; ks < 4; ks++) {
            uint32_t a[4];
            LDSM_X4(a, Qb + q_r * 144 + (ks * 16 + q_k) * 2);
#pragma unroll
            for (int ntp = 0; ntp < 4; ntp++) {
                uint32_t b[4];
                LDSM_X4(b, Kb + (ntp * 16 + k_n) * 144 + (ks * 16 + k_k) * 2);
                mma_f16(sf[2 * ntp],     a, b[0], b[1]);
                mma_f16(sf[2 * ntp + 1], a, b[2], b[3]);
            }
        }

        float mx0 = -1e30f, mx1 = -1e30f;
#pragma unroll
        for (int nt = 0; nt < 8; nt++) {
            mx0 = fmaxf(mx0, fmaxf(sf[nt][0], sf[nt][1]));
            mx1 = fmaxf(mx1, fmaxf(sf[nt][2], sf[nt][3]));
        }
        mx0 = fmaxf(mx0, __shfl_xor_sync(0xffffffffu, mx0, 1));
        mx0 = fmaxf(mx0, __shfl_xor_sync(0xffffffffu, mx0, 2));
        mx1 = fmaxf(mx1, __shfl_xor_sync(0xffffffffu, mx1, 1));
        mx1 = fmaxf(mx1, __shfl_xor_sync(0xffffffffu, mx1, 2));
        const float mn0 = fmaxf(mrun0, mx0);
        const float mn1 = fmaxf(mrun1, mx1);
        const float cor0 = __expf(mrun0 - mn0);
        const float cor1 = __expf(mrun1 - mn1);
        float ls0 = 0.f, ls1 = 0.f;
        uint32_t pf0[8], pf1[8];
#pragma unroll
        for (int nt = 0; nt < 8; nt++) {
            __half2 h0 = __floats2half2_rn(__expf(sf[nt][0] - mn0), __expf(sf[nt][1] - mn0));
            __half2 h1 = __floats2half2_rn(__expf(sf[nt][2] - mn1), __expf(sf[nt][3] - mn1));
            float2 f0 = __half22float2(h0);
            float2 f1 = __half22float2(h1);
            ls0 += f0.x + f0.y;
            ls1 += f1.x + f1.y;
            pf0[nt] = *reinterpret_cast<uint32_t*>(&h0);
            pf1[nt] = *reinterpret_cast<uint32_t*>(&h1);
        }
        ls0 += __shfl_xor_sync(0xffffffffu, ls0, 1);
        ls0 += __shfl_xor_sync(0xffffffffu, ls0, 2);
        ls1 += __shfl_xor_sync(0xffffffffu, ls1, 1);
        ls1 += __shfl_xor_sync(0xffffffffu, ls1, 2);
        lrun0 = lrun0 * cor0 + ls0;
        lrun1 = lrun1 * cor1 + ls1;
        mrun0 = mn0; mrun1 = mn1;
#pragma unroll
        for (int dt = 0; dt < 8; dt++) {
            Of[dt][0] *= cor0; Of[dt][1] *= cor0;
            Of[dt][2] *= cor1; Of[dt][3] *= cor1;
        }

#pragma unroll
        for (int ks = 0; ks < 4; ks++) {
            uint32_t a[4] = {pf0[2 * ks], pf1[2 * ks], pf0[2 * ks + 1], pf1[2 * ks + 1]};
#pragma unroll
            for (int dtp = 0; dtp < 4; dtp++) {
                uint32_t b[4];
                LDSM_X4T(b, Vb + (ks * 16 + v_key) * 144 + (dtp * 16 + v_d) * 2);
                mma_f16(Of[2 * dtp],     a, b[0], b[1]);
                mma_f16(Of[2 * dtp + 1], a, b[2], b[3]);
            }
        }

        __syncthreads();
        if (tsel + 2 < TOPK) { K4_KV_ISSUE(tsel + 2); }
        CP_COMMIT();
    }

    const float inv0 = 1.f / lrun0;
    const float inv1 = 1.f / lrun1;
    uint32_t* d0 = (uint32_t*)g_aoh + ((size_t)np * W2 + mw + lr)     * 256 + head * 32;
    uint32_t* d1 = (uint32_t*)g_aoh + ((size_t)np * W2 + mw + lr + 8) * 256 + head * 32;
#pragma unroll
    for (int dt = 0; dt < 8; dt++) {
        d0[dt * 4 + lq] = pack2(Of[dt][0] * inv0, Of[dt][1] * inv0);
        d1[dt * 4 + lq] = pack2(Of[dt][2] * inv1, Of[dt][3] * inv1);
    }
#undef K4_KV_ISSUE
}

// ===========================================================================
// Kernel 5: LePE depthwise 3x3 + attn out, half2 channels, NCHW fp32 output.
// ===========================================================================
__global__ __launch_bounds__(256) void k5_out(const float* __restrict__ wlepe,
                                              const float* __restrict__ blepe,
                                              float* __restrict__ out) {
    __shared__ float2 stage[64][33];   // [pix][c2]
    const int cb = blockIdx.x;
    const int p  = blockIdx.y;
    const int n  = blockIdx.z;
    const int c0 = cb * 64;
    const int t  = threadIdx.x;
    const int c2 = t & 31;
    const int pr = t >> 5;

    const int ce = c0 + 2 * c2;
    float wl0[9], wl1[9];
#pragma unroll
    for (int k = 0; k < 9; k++) {
        wl0[k] = wlepe[ce * 9 + k];
        wl1[k] = wlepe[(ce + 1) * 9 + k];
    }
    const float bias0 = blepe[ce];
    const float bias1 = blepe[ce + 1];

    const int wh0 = (p / NWIN) * 8;
    const int ww0 = (p % NWIN) * 8;

    for (int pg = 0; pg < 8; pg++) {
        int pix = pg * 8 + pr;
        int ih = pix >> 3, iw = pix & 7;
        int h = wh0 + ih, w = ww0 + iw;
        float a0 = bias0, a1 = bias1;
#pragma unroll
        for (int kh = 0; kh < 3; kh++) {
            int hh = h + kh - 1;
            if (hh < 0 || hh >= H_IMG) continue;
#pragma unroll
            for (int kw = 0; kw < 3; kw++) {
                int ww = w + kw - 1;
                if (ww < 0 || ww >= W_IMG) continue;
                int pp   = (hh >> 3) * NWIN + (ww >> 3);
                int ppix = ((hh & 7) << 3) + (ww & 7);
                uint32_t vv = *(const uint32_t*)&g_kvh[
                    ((size_t)(n * P2 + pp) * W2 + ppix) * 1024 + 512 + ce];
                float2 vf = __half22float2(*reinterpret_cast<__half2*>(&vv));
                a0 += vf.x * wl0[kh * 3 + kw];
                a1 += vf.y * wl1[kh * 3 + kw];
            }
        }
        uint32_t av = *(const uint32_t*)&g_aoh[((size_t)(n * P2 + p) * W2 + pix) * 512 + ce];
        float2 af = __half22float2(*reinterpret_cast<__half2*>(&av));
        stage[pix][c2] = make_float2(a0 + af.x, a1 + af.y);
    }
    __syncthreads();

    const int wc = t >> 2;
    const int wx = (t & 3) * 2;
    const int cpair = wc >> 1;
    const int csel  = wc & 1;
    const size_t obase = ((size_t)n * C_DIM + c0 + wc) * HW;
    for (int h = 0; h < 8; h++) {
        float2 s0 = stage[h * 8 + wx][cpair];
        float2 s1 = stage[h * 8 + wx + 1][cpair];
        float2 v = csel ? make_float2(s0.y, s1.y) : make_float2(s0.x, s1.x);
        *(float2*)(out + obase + (size_t)(wh0 + h) * W_IMG + ww0 + wx) = v;
    }
}

// ===========================================================================
extern "C" void kernel_launch(void* const* d_in, const int* in_sizes, int n_in,
                              void* d_out, int out_size) {
    const float* x      = (const float*)d_in[0];
    const float* w_qkv  = (const float*)d_in[1];
    const float* b_qkv  = (const float*)d_in[2];
    const float* w_lepe = (const float*)d_in[3];
    const float* b_lepe = (const float*)d_in[4];
    float* out = (float*)d_out;

    cudaFuncSetAttribute(k1_qkv_tc, cudaFuncAttributeMaxDynamicSharedMemorySize, K1_SMEM);
    cudaFuncSetAttribute(k4_attn_tc, cudaFuncAttributeMaxDynamicSharedMemorySize, K4_SMEM);

    kd_nop<<<1, 32>>>();
    kd_nop<<<1, 32>>>();
    k0_half<<<25088, 256>>>(x, w_qkv);
    k1_qkv_tc<<<dim3(12, 392), 128, K1_SMEM>>>(b_qkv);
    k2_mean<<<784, 256>>>();
    k3_route<<<784, 128>>>();
    k4_attn_tc<<<dim3(HEADS, N_IMG * P2), 128, K4_SMEM>>>();
    k5_out<<<dim3(8, P2, N_IMG), 256>>>(w_lepe, b_lepe, out);
}

// round 16
// speedup vs baseline: 1.0026x; 1.0026x over previous
#include <cuda_runtime.h>
#include <cuda_fp16.h>
#include <cstdint>

// ---------------------------------------------------------------------------
// DeBiLevelRoutingAttention block. Round 15: k1 3-stage pipeline + 3 CTAs/SM
// (launch_bounds(128,3)) for 12 warps/SM of latency hiding; warp tile 64x64
// (128B LDSM per HMMA) retained from R14.
// ---------------------------------------------------------------------------

#define N_IMG  16
#define C_DIM  512
#define H_IMG  56
#define W_IMG  56
#define HW     3136
#define CHW    (C_DIM * HW)
#define QKC    512
#define NWIN   7
#define P2     49
#define W2     64
#define TOPK   4
#define HEADS  8
#define HD     64
#define SCALE  0.04419417382415922f   // 512^-0.5

// ----------------------------- scratch ------------------------------------
__device__ float g_qwin[(size_t)N_IMG * P2 * C_DIM];
__device__ float g_kwin[(size_t)N_IMG * P2 * C_DIM];
__device__ int   g_idx [N_IMG * P2 * TOPK];
__device__ __align__(16) __half g_xh [(size_t)N_IMG * CHW];
__device__ __align__(16) __half g_wh [1536 * 512];
__device__ __align__(16) __half g_qh [(size_t)N_IMG * P2 * W2 * 512];   // pre-scaled
__device__ __align__(16) __half g_kvh[(size_t)N_IMG * P2 * W2 * 1024];
__device__ __align__(16) __half g_aoh[(size_t)N_IMG * P2 * W2 * 512];

// ----------------------------- helpers ------------------------------------
__device__ __forceinline__ uint32_t pack2(float lo, float hi) {
    __half2 h = __floats2half2_rn(lo, hi);
    return *reinterpret_cast<uint32_t*>(&h);
}
__device__ __forceinline__ uint32_t smem_u32(const void* p) {
    return (uint32_t)__cvta_generic_to_shared(p);
}
__device__ __forceinline__ void mma_f16(float c[4], const uint32_t a[4],
                                        uint32_t b0, uint32_t b1) {
    asm volatile(
        "mma.sync.aligned.m16n8k16.row.col.f32.f16.f16.f32 "
        "{%0,%1,%2,%3}, {%4,%5,%6,%7}, {%8,%9}, {%0,%1,%2,%3};"
        : "+f"(c[0]), "+f"(c[1]), "+f"(c[2]), "+f"(c[3])
        : "r"(a[0]), "r"(a[1]), "r"(a[2]), "r"(a[3]), "r"(b0), "r"(b1));
}
#define CP_ASYNC16(dst, src) \
    asm volatile("cp.async.cg.shared.global [%0], [%1], 16;" \
                 :: "r"(dst), "l"(src) : "memory")
#define CP_COMMIT() asm volatile("cp.async.commit_group;" ::: "memory")
#define CP_WAIT(n)  asm volatile("cp.async.wait_group %0;" :: "n"(n) : "memory")
#define LDSM_X4(r, a) \
    asm volatile("ldmatrix.sync.aligned.m8n8.x4.shared.b16 {%0,%1,%2,%3}, [%4];" \
        : "=r"((r)[0]), "=r"((r)[1]), "=r"((r)[2]), "=r"((r)[3]) : "r"(a))
#define LDSM_X4T(r, a) \
    asm volatile("ldmatrix.sync.aligned.m8n8.x4.trans.shared.b16 {%0,%1,%2,%3}, [%4];" \
        : "=r"((r)[0]), "=r"((r)[1]), "=r"((r)[2]), "=r"((r)[3]) : "r"(a))

// ===========================================================================
// Dummy no-op kernel: keeps ncu's captured launch on k1.
// ===========================================================================
__global__ void kd_nop() {}

// ===========================================================================
// Kernel 0: convert x and w_qkv to fp16.
// ===========================================================================
__global__ __launch_bounds__(256) void k0_half(const float* __restrict__ x,
                                               const float* __restrict__ w) {
    const int i = blockIdx.x * 256 + threadIdx.x;
    const int NX4 = (N_IMG * CHW) >> 2;
    const int NW4 = (1536 * 512) >> 2;
    if (i < NX4) {
        float4 v = ((const float4*)x)[i];
        uint32_t* d = (uint32_t*)g_xh;
        d[2 * i]     = pack2(v.x, v.y);
        d[2 * i + 1] = pack2(v.z, v.w);
    }
    if (i < NW4) {
        float4 v = ((const float4*)w)[i];
        uint32_t* d = (uint32_t*)g_wh;
        d[2 * i]     = pack2(v.x, v.y);
        d[2 * i + 1] = pack2(v.z, v.w);
    }
}

// ===========================================================================
// Kernel 1: QKV GEMM, fp16 mma. Block 128x128, 4 warps (2Mx2N), warp 64x64.
// K-chunk 32, 3-stage cp.async, 3 CTAs/SM. A smem [k][m] pitch 272B;
// B smem [n][k] pitch 80B. Per k16 step: 8 LDSM / 32 HMMA.
// ===========================================================================
#define K1_ABYTES 8704                 // 32 * 272
#define K1_BBYTES 10240                // 128 * 80
#define K1_STAGE  (K1_ABYTES + K1_BBYTES)
#define K1_SMEM   (3 * K1_STAGE)       // 56832

__global__ __launch_bounds__(128, 3) void k1_qkv_tc(const float* __restrict__ bqkv) {
    extern __shared__ char smc[];
    const uint32_t sb = smem_u32(smc);
    const int t  = threadIdx.x;
    const int o0 = blockIdx.x * 128;
    const int m0 = blockIdx.y * 128;

    const int wid = t >> 5, lane = t & 31;
    const int mw = (wid & 1) * 64;
    const int nw = (wid >> 1) * 64;
    const int grp = lane >> 3, li = lane & 7;
    const int a_k = li + ((grp & 2) ? 8 : 0);
    const int a_m = (grp & 1) ? 8 : 0;
    const int b_n = li + ((grp & 2) ? 8 : 0);
    const int b_k = (grp & 1) ? 8 : 0;
    const int lr = lane >> 2, lq = lane & 3;

    // A loader: 4 iters x 128 thr cover 32 k-rows x 128 m (8-pixel chunks).
    const int a_mh = (t & 15) * 8;
    const int mA   = m0 + a_mh;
    const int nA   = mA / HW;
    const int hwA  = mA - nA * HW;
    const __half* axp = g_xh + (size_t)nA * CHW + hwA;
    const int a_kr0 = t >> 4;            // + 8*i
    // B loader: 4 iters x 128 thr cover 128 n-rows x 32 k.
    const int b_bn0 = t >> 2;            // + 32*i
    const int b_bh  = (t & 3) * 8;

    float c[4][8][4];
#pragma unroll
    for (int mt = 0; mt < 4; mt++)
#pragma unroll
        for (int nt = 0; nt < 8; nt++)
#pragma unroll
            for (int i = 0; i < 4; i++) c[mt][nt][i] = 0.f;

#define K1_ISSUE(kc_) do {                                                    \
    const int s_ = (kc_) % 3;                                                 \
    const uint32_t ab_ = sb + s_ * K1_STAGE;                                  \
    const uint32_t bb_ = ab_ + K1_ABYTES;                                     \
    _Pragma("unroll")                                                         \
    for (int i_ = 0; i_ < 4; i_++) {                                          \
        const int kr_ = a_kr0 + 8 * i_;                                       \
        CP_ASYNC16(ab_ + kr_ * 272 + a_mh * 2,                                \
                   axp + (size_t)((kc_) * 32 + kr_) * HW);                    \
        const int bn_ = b_bn0 + 32 * i_;                                      \
        CP_ASYNC16(bb_ + bn_ * 80 + b_bh * 2,                                 \
                   g_wh + (size_t)(o0 + bn_) * 512 + (kc_) * 32 + b_bh);      \
    }                                                                         \
} while (0)

    K1_ISSUE(0); CP_COMMIT();
    K1_ISSUE(1); CP_COMMIT();

    for (int kc = 0; kc < 16; kc++) {
        CP_WAIT(1);
        __syncthreads();
        if (kc + 2 < 16) { K1_ISSUE(kc + 2); }
        CP_COMMIT();
        const uint32_t ab = sb + (kc % 3) * K1_STAGE;
        const uint32_t bb = ab + K1_ABYTES;
#pragma unroll
        for (int ks = 0; ks < 2; ks++) {
            uint32_t a[4][4];
#pragma unroll
            for (int mt = 0; mt < 4; mt++)
                LDSM_X4T(a[mt], ab + (ks * 16 + a_k) * 272 + (mw + mt * 16 + a_m) * 2);
            uint32_t b[4][4];
#pragma unroll
            for (int ntp = 0; ntp < 4; ntp++)
                LDSM_X4(b[ntp], bb + (nw + ntp * 16 + b_n) * 80 + (ks * 16 + b_k) * 2);
#pragma unroll
            for (int mt = 0; mt < 4; mt++)
#pragma unroll
                for (int ntp = 0; ntp < 4; ntp++) {
                    mma_f16(c[mt][2 * ntp],     a[mt], b[ntp][0], b[ntp][1]);
                    mma_f16(c[mt][2 * ntp + 1], a[mt], b[ntp][2], b[ntp][3]);
                }
        }
    }

    const bool isq = (o0 < QKC);
#pragma unroll
    for (int mt = 0; mt < 4; mt++) {
#pragma unroll
        for (int half = 0; half < 2; half++) {
            const int row = mw + mt * 16 + lr + half * 8;
            const int m   = m0 + row;
            const int n   = m / HW;
            const int hw  = m - n * HW;
            const int h   = hw / W_IMG;
            const int wp  = hw - h * W_IMG;
            const int p   = (h >> 3) * NWIN + (wp >> 3);
            const int pix = ((h & 7) << 3) + (wp & 7);
            const size_t npix = (size_t)((n * P2 + p) * W2 + pix);
            uint32_t* dsth = isq ? ((uint32_t*)g_qh  + npix * 256 + (o0 >> 1))
                                 : ((uint32_t*)g_kvh + npix * 512 + ((o0 - QKC) >> 1));
#pragma unroll
            for (int nt = 0; nt < 8; nt++) {
                const int col = nw + nt * 8 + lq * 2;
                float vx = c[mt][nt][half * 2 + 0] + bqkv[o0 + col];
                float vy = c[mt][nt][half * 2 + 1] + bqkv[o0 + col + 1];
                dsth[col >> 1] = isq ? pack2(vx * SCALE, vy * SCALE) : pack2(vx, vy);
            }
        }
    }
#undef K1_ISSUE
}

// ===========================================================================
// Kernel 2: window means from fp16 q/kv, fp32 accumulation.
// ===========================================================================
__global__ __launch_bounds__(256) void k2_mean() {
    const int np = blockIdx.x;
    const int c2 = threadIdx.x;
    const uint32_t* qb = (const uint32_t*)g_qh  + (size_t)np * W2 * 256 + c2;
    const uint32_t* kb = (const uint32_t*)g_kvh + (size_t)np * W2 * 512 + c2;
    float sqx = 0.f, sqy = 0.f, skx = 0.f, sky = 0.f;
#pragma unroll 8
    for (int pix = 0; pix < W2; pix++) {
        uint32_t qv = qb[(size_t)pix * 256];
        uint32_t kv = kb[(size_t)pix * 512];
        float2 qf = __half22float2(*reinterpret_cast<__half2*>(&qv));
        float2 kf = __half22float2(*reinterpret_cast<__half2*>(&kv));
        sqx += qf.x; sqy += qf.y;
        skx += kf.x; sky += kf.y;
    }
    *(float2*)(g_qwin + (size_t)np * 512 + 2 * c2) = make_float2(sqx * (1.f/64.f), sqy * (1.f/64.f));
    *(float2*)(g_kwin + (size_t)np * 512 + 2 * c2) = make_float2(skx * (1.f/64.f), sky * (1.f/64.f));
}

// ===========================================================================
// Kernel 3: routing logits + top-4 (warp-parallel argmax). grid 784 x 128.
// ===========================================================================
__global__ __launch_bounds__(128) void k3_route() {
    __shared__ float qs[512];
    __shared__ float lg[P2];
    const int np = blockIdx.x;
    const int n  = np / P2;
    const int t  = threadIdx.x;
    for (int c = t; c < 512; c += 128)
        qs[c] = g_qwin[(size_t)np * 512 + c];
    __syncthreads();
    {
        const int win = (t >> 1) < P2 ? (t >> 1) : (P2 - 1);
        const int hf  = t & 1;
        const float4* kr = (const float4*)(g_kwin + (size_t)(n * P2 + win) * 512) + hf * 64;
        const float*  qh = qs + hf * 256;
        float s = 0.f;
#pragma unroll 8
        for (int c4 = 0; c4 < 64; c4++) {
            float4 k4 = kr[c4];
            s += qh[c4 * 4 + 0] * k4.x + qh[c4 * 4 + 1] * k4.y +
                 qh[c4 * 4 + 2] * k4.z + qh[c4 * 4 + 3] * k4.w;
        }
        s += __shfl_xor_sync(0xffffffffu, s, 1);
        if (hf == 0 && (t >> 1) < P2) lg[win] = s;
    }
    __syncthreads();
    if (t < 32) {
        float v0 = (t < P2)      ? lg[t]      : -1e30f;
        float v1 = (t + 32 < P2) ? lg[t + 32] : -1e30f;
#pragma unroll
        for (int sel = 0; sel < TOPK; sel++) {
            float m; int idx;
            if (v0 >= v1) { m = v0; idx = t; } else { m = v1; idx = t + 32; }
#pragma unroll
            for (int off = 16; off; off >>= 1) {
                float om = __shfl_xor_sync(0xffffffffu, m, off);
                int   oi = __shfl_xor_sync(0xffffffffu, idx, off);
                if (om > m || (om == m && oi < idx)) { m = om; idx = oi; }
            }
            if (t == 0) g_idx[np * TOPK + sel] = idx;
            const int wsel = __shfl_sync(0xffffffffu, idx, 0);
            if (wsel == t)      v0 = -1e30f;
            if (wsel == t + 32) v1 = -1e30f;
        }
    }
}

// ===========================================================================
// Kernel 4: attention, fp16 mma + double-buffered cp.async KV (unchanged).
// ===========================================================================
#define K4_TILE 9216                   // 64 * 144
#define K4_SMEM (5 * K4_TILE)

__global__ __launch_bounds__(128) void k4_attn_tc() {
    extern __shared__ char smc[];
    const uint32_t sb = smem_u32(smc);
    const uint32_t Qb = sb;

    const int head = blockIdx.x;
    const int np   = blockIdx.y;
    const int n    = np / P2;
    const int t    = threadIdx.x;
    const int wid  = t >> 5;
    const int lane = t & 31;
    const int mw   = wid * 16;
    const int lr   = lane >> 2;
    const int lq   = lane & 3;
    const int grp  = lane >> 3, li = lane & 7;

    const int q_r   = mw + li + ((grp & 1) ? 8 : 0);
    const int q_k   = (grp & 2) ? 8 : 0;
    const int k_n   = li + ((grp & 2) ? 8 : 0);
    const int k_k   = (grp & 1) ? 8 : 0;
    const int v_key = li + ((grp & 1) ? 8 : 0);
    const int v_d   = (grp & 2) ? 8 : 0;

    int widx[TOPK];
#pragma unroll
    for (int i = 0; i < TOPK; i++) widx[i] = g_idx[np * TOPK + i];

#define K4_KV_ISSUE(ts_) do {                                                   \
    const int s_ = (ts_) & 1;                                                   \
    const uint32_t Kb_ = sb + (1 + 2 * s_) * K4_TILE;                           \
    const uint32_t Vb_ = Kb_ + K4_TILE;                                         \
    const __half* kvsrc_ = g_kvh + (size_t)(n * P2 + widx[ts_]) * 64 * 1024 + head * HD; \
    _Pragma("unroll")                                                           \
    for (int i_ = 0; i_ < 4; i_++) {                                            \
        int cq_ = i_ * 128 + t;                                                 \
        int pix_ = cq_ >> 3, h8_ = (cq_ & 7) * 8;                               \
        CP_ASYNC16(Kb_ + pix_ * 144 + h8_ * 2, kvsrc_ + (size_t)pix_ * 1024 + h8_);       \
        CP_ASYNC16(Vb_ + pix_ * 144 + h8_ * 2, kvsrc_ + (size_t)pix_ * 1024 + 512 + h8_); \
    }                                                                           \
} while (0)

    {
        const __half* qsrc = g_qh + (size_t)np * 64 * 512 + head * HD;
#pragma unroll
        for (int i = 0; i < 4; i++) {
            int cq = i * 128 + t;
            int pix = cq >> 3, h8 = (cq & 7) * 8;
            CP_ASYNC16(Qb + pix * 144 + h8 * 2, qsrc + (size_t)pix * 512 + h8);
        }
        K4_KV_ISSUE(0);
        CP_COMMIT();
        K4_KV_ISSUE(1);
        CP_COMMIT();
    }

    float Of[8][4];
#pragma unroll
    for (int dt = 0; dt < 8; dt++)
#pragma unroll
        for (int i = 0; i < 4; i++) Of[dt][i] = 0.f;
    float mrun0 = -1e30f, mrun1 = -1e30f, lrun0 = 0.f, lrun1 = 0.f;

    for (int tsel = 0; tsel < TOPK; tsel++) {
        CP_WAIT(1);
        __syncthreads();
        const uint32_t Kb = sb + (1 + 2 * (tsel & 1)) * K4_TILE;
        const uint32_t Vb = Kb + K4_TILE;

        float sf[8][4];
#pragma unroll
        for (int nt = 0; nt < 8; nt++)
#pragma unroll
            for (int i = 0; i < 4; i++) sf[nt][i] = 0.f;
#pragma unroll
        for (int ks = 0; ks < 4; ks++) {
            uint32_t a[4];
            LDSM_X4(a, Qb + q_r * 144 + (ks * 16 + q_k) * 2);
#pragma unroll
            for (int ntp = 0; ntp < 4; ntp++) {
                uint32_t b[4];
                LDSM_X4(b, Kb + (ntp * 16 + k_n) * 144 + (ks * 16 + k_k) * 2);
                mma_f16(sf[2 * ntp],     a, b[0], b[1]);
                mma_f16(sf[2 * ntp + 1], a, b[2], b[3]);
            }
        }

        float mx0 = -1e30f, mx1 = -1e30f;
#pragma unroll
        for (int nt = 0; nt < 8; nt++) {
            mx0 = fmaxf(mx0, fmaxf(sf[nt][0], sf[nt][1]));
            mx1 = fmaxf(mx1, fmaxf(sf[nt][2], sf[nt][3]));
        }
        mx0 = fmaxf(mx0, __shfl_xor_sync(0xffffffffu, mx0, 1));
        mx0 = fmaxf(mx0, __shfl_xor_sync(0xffffffffu, mx0, 2));
        mx1 = fmaxf(mx1, __shfl_xor_sync(0xffffffffu, mx1, 1));
        mx1 = fmaxf(mx1, __shfl_xor_sync(0xffffffffu, mx1, 2));
        const float mn0 = fmaxf(mrun0, mx0);
        const float mn1 = fmaxf(mrun1, mx1);
        const float cor0 = __expf(mrun0 - mn0);
        const float cor1 = __expf(mrun1 - mn1);
        float ls0 = 0.f, ls1 = 0.f;
        uint32_t pf0[8], pf1[8];
#pragma unroll
        for (int nt = 0; nt < 8; nt++) {
            __half2 h0 = __floats2half2_rn(__expf(sf[nt][0] - mn0), __expf(sf[nt][1] - mn0));
            __half2 h1 = __floats2half2_rn(__expf(sf[nt][2] - mn1), __expf(sf[nt][3] - mn1));
            float2 f0 = __half22float2(h0);
            float2 f1 = __half22float2(h1);
            ls0 += f0.x + f0.y;
            ls1 += f1.x + f1.y;
            pf0[nt] = *reinterpret_cast<uint32_t*>(&h0);
            pf1[nt] = *reinterpret_cast<uint32_t*>(&h1);
        }
        ls0 += __shfl_xor_sync(0xffffffffu, ls0, 1);
        ls0 += __shfl_xor_sync(0xffffffffu, ls0, 2);
        ls1 += __shfl_xor_sync(0xffffffffu, ls1, 1);
        ls1 += __shfl_xor_sync(0xffffffffu, ls1, 2);
        lrun0 = lrun0 * cor0 + ls0;
        lrun1 = lrun1 * cor1 + ls1;
        mrun0 = mn0; mrun1 = mn1;
#pragma unroll
        for (int dt = 0; dt < 8; dt++) {
            Of[dt][0] *= cor0; Of[dt][1] *= cor0;
            Of[dt][2] *= cor1; Of[dt][3] *= cor1;
        }

#pragma unroll
        for (int ks = 0; ks < 4; ks++) {
            uint32_t a[4] = {pf0[2 * ks], pf1[2 * ks], pf0[2 * ks + 1], pf1[2 * ks + 1]};
#pragma unroll
            for (int dtp = 0; dtp < 4; dtp++) {
                uint32_t b[4];
                LDSM_X4T(b, Vb + (ks * 16 + v_key) * 144 + (dtp * 16 + v_d) * 2);
                mma_f16(Of[2 * dtp],     a, b[0], b[1]);
                mma_f16(Of[2 * dtp + 1], a, b[2], b[3]);
            }
        }

        __syncthreads();
        if (tsel + 2 < TOPK) { K4_KV_ISSUE(tsel + 2); }
        CP_COMMIT();
    }

    const float inv0 = 1.f / lrun0;
    const float inv1 = 1.f / lrun1;
    uint32_t* d0 = (uint32_t*)g_aoh + ((size_t)np * W2 + mw + lr)     * 256 + head * 32;
    uint32_t* d1 = (uint32_t*)g_aoh + ((size_t)np * W2 + mw + lr + 8) * 256 + head * 32;
#pragma unroll
    for (int dt = 0; dt < 8; dt++) {
        d0[dt * 4 + lq] = pack2(Of[dt][0] * inv0, Of[dt][1] * inv0);
        d1[dt * 4 + lq] = pack2(Of[dt][2] * inv1, Of[dt][3] * inv1);
    }
#undef K4_KV_ISSUE
}

// ===========================================================================
// Kernel 5: LePE depthwise 3x3 + attn out, half2 channels, NCHW fp32 output.
// ===========================================================================
__global__ __launch_bounds__(256) void k5_out(const float* __restrict__ wlepe,
                                              const float* __restrict__ blepe,
                                              float* __restrict__ out) {
    __shared__ float2 stage[64][33];   // [pix][c2]
    const int cb = blockIdx.x;
    const int p  = blockIdx.y;
    const int n  = blockIdx.z;
    const int c0 = cb * 64;
    const int t  = threadIdx.x;
    const int c2 = t & 31;
    const int pr = t >> 5;

    const int ce = c0 + 2 * c2;
    float wl0[9], wl1[9];
#pragma unroll
    for (int k = 0; k < 9; k++) {
        wl0[k] = wlepe[ce * 9 + k];
        wl1[k] = wlepe[(ce + 1) * 9 + k];
    }
    const float bias0 = blepe[ce];
    const float bias1 = blepe[ce + 1];

    const int wh0 = (p / NWIN) * 8;
    const int ww0 = (p % NWIN) * 8;

    for (int pg = 0; pg < 8; pg++) {
        int pix = pg * 8 + pr;
        int ih = pix >> 3, iw = pix & 7;
        int h = wh0 + ih, w = ww0 + iw;
        float a0 = bias0, a1 = bias1;
#pragma unroll
        for (int kh = 0; kh < 3; kh++) {
            int hh = h + kh - 1;
            if (hh < 0 || hh >= H_IMG) continue;
#pragma unroll
            for (int kw = 0; kw < 3; kw++) {
                int ww = w + kw - 1;
                if (ww < 0 || ww >= W_IMG) continue;
                int pp   = (hh >> 3) * NWIN + (ww >> 3);
                int ppix = ((hh & 7) << 3) + (ww & 7);
                uint32_t vv = *(const uint32_t*)&g_kvh[
                    ((size_t)(n * P2 + pp) * W2 + ppix) * 1024 + 512 + ce];
                float2 vf = __half22float2(*reinterpret_cast<__half2*>(&vv));
                a0 += vf.x * wl0[kh * 3 + kw];
                a1 += vf.y * wl1[kh * 3 + kw];
            }
        }
        uint32_t av = *(const uint32_t*)&g_aoh[((size_t)(n * P2 + p) * W2 + pix) * 512 + ce];
        float2 af = __half22float2(*reinterpret_cast<__half2*>(&av));
        stage[pix][c2] = make_float2(a0 + af.x, a1 + af.y);
    }
    __syncthreads();

    const int wc = t >> 2;
    const int wx = (t & 3) * 2;
    const int cpair = wc >> 1;
    const int csel  = wc & 1;
    const size_t obase = ((size_t)n * C_DIM + c0 + wc) * HW;
    for (int h = 0; h < 8; h++) {
        float2 s0 = stage[h * 8 + wx][cpair];
        float2 s1 = stage[h * 8 + wx + 1][cpair];
        float2 v = csel ? make_float2(s0.y, s1.y) : make_float2(s0.x, s1.x);
        *(float2*)(out + obase + (size_t)(wh0 + h) * W_IMG + ww0 + wx) = v;
    }
}

// ===========================================================================
extern "C" void kernel_launch(void* const* d_in, const int* in_sizes, int n_in,
                              void* d_out, int out_size) {
    const float* x      = (const float*)d_in[0];
    const float* w_qkv  = (const float*)d_in[1];
    const float* b_qkv  = (const float*)d_in[2];
    const float* w_lepe = (const float*)d_in[3];
    const float* b_lepe = (const float*)d_in[4];
    float* out = (float*)d_out;

    cudaFuncSetAttribute(k1_qkv_tc, cudaFuncAttributeMaxDynamicSharedMemorySize, K1_SMEM);
    cudaFuncSetAttribute(k4_attn_tc, cudaFuncAttributeMaxDynamicSharedMemorySize, K4_SMEM);

    kd_nop<<<1, 32>>>();
    kd_nop<<<1, 32>>>();
    k0_half<<<25088, 256>>>(x, w_qkv);
    k1_qkv_tc<<<dim3(12, 392), 128, K1_SMEM>>>(b_qkv);
    k2_mean<<<784, 256>>>();
    k3_route<<<784, 128>>>();
    k4_attn_tc<<<dim3(HEADS, N_IMG * P2), 128, K4_SMEM>>>();
    k5_out<<<dim3(8, P2, N_IMG), 256>>>(w_lepe, b_lepe, out);
}

// round 17
// speedup vs baseline: 1.0328x; 1.0302x over previous
#include <cuda_runtime.h>
#include <cuda_fp16.h>
#include <cstdint>

// ---------------------------------------------------------------------------
// DeBiLevelRoutingAttention block. Round 17: k1 reverted to R14 optimum;
// k4 Q-fragments hoisted to registers; nop launches removed (ncu -> k5).
// ---------------------------------------------------------------------------

#define N_IMG  16
#define C_DIM  512
#define H_IMG  56
#define W_IMG  56
#define HW     3136
#define CHW    (C_DIM * HW)
#define QKC    512
#define NWIN   7
#define P2     49
#define W2     64
#define TOPK   4
#define HEADS  8
#define HD     64
#define SCALE  0.04419417382415922f   // 512^-0.5

// ----------------------------- scratch ------------------------------------
__device__ float g_qwin[(size_t)N_IMG * P2 * C_DIM];
__device__ float g_kwin[(size_t)N_IMG * P2 * C_DIM];
__device__ int   g_idx [N_IMG * P2 * TOPK];
__device__ __align__(16) __half g_xh [(size_t)N_IMG * CHW];
__device__ __align__(16) __half g_wh [1536 * 512];
__device__ __align__(16) __half g_qh [(size_t)N_IMG * P2 * W2 * 512];   // pre-scaled
__device__ __align__(16) __half g_kvh[(size_t)N_IMG * P2 * W2 * 1024];
__device__ __align__(16) __half g_aoh[(size_t)N_IMG * P2 * W2 * 512];

// ----------------------------- helpers ------------------------------------
__device__ __forceinline__ uint32_t pack2(float lo, float hi) {
    __half2 h = __floats2half2_rn(lo, hi);
    return *reinterpret_cast<uint32_t*>(&h);
}
__device__ __forceinline__ uint32_t smem_u32(const void* p) {
    return (uint32_t)__cvta_generic_to_shared(p);
}
__device__ __forceinline__ void mma_f16(float c[4], const uint32_t a[4],
                                        uint32_t b0, uint32_t b1) {
    asm volatile(
        "mma.sync.aligned.m16n8k16.row.col.f32.f16.f16.f32 "
        "{%0,%1,%2,%3}, {%4,%5,%6,%7}, {%8,%9}, {%0,%1,%2,%3};"
        : "+f"(c[0]), "+f"(c[1]), "+f"(c[2]), "+f"(c[3])
        : "r"(a[0]), "r"(a[1]), "r"(a[2]), "r"(a[3]), "r"(b0), "r"(b1));
}
#define CP_ASYNC16(dst, src) \
    asm volatile("cp.async.cg.shared.global [%0], [%1], 16;" \
                 :: "r"(dst), "l"(src) : "memory")
#define CP_COMMIT() asm volatile("cp.async.commit_group;" ::: "memory")
#define CP_WAIT(n)  asm volatile("cp.async.wait_group %0;" :: "n"(n) : "memory")
#define LDSM_X4(r, a) \
    asm volatile("ldmatrix.sync.aligned.m8n8.x4.shared.b16 {%0,%1,%2,%3}, [%4];" \
        : "=r"((r)[0]), "=r"((r)[1]), "=r"((r)[2]), "=r"((r)[3]) : "r"(a))
#define LDSM_X4T(r, a) \
    asm volatile("ldmatrix.sync.aligned.m8n8.x4.trans.shared.b16 {%0,%1,%2,%3}, [%4];" \
        : "=r"((r)[0]), "=r"((r)[1]), "=r"((r)[2]), "=r"((r)[3]) : "r"(a))

// ===========================================================================
// Kernel 0: convert x and w_qkv to fp16.
// ===========================================================================
__global__ __launch_bounds__(256) void k0_half(const float* __restrict__ x,
                                               const float* __restrict__ w) {
    const int i = blockIdx.x * 256 + threadIdx.x;
    const int NX4 = (N_IMG * CHW) >> 2;
    const int NW4 = (1536 * 512) >> 2;
    if (i < NX4) {
        float4 v = ((const float4*)x)[i];
        uint32_t* d = (uint32_t*)g_xh;
        d[2 * i]     = pack2(v.x, v.y);
        d[2 * i + 1] = pack2(v.z, v.w);
    }
    if (i < NW4) {
        float4 v = ((const float4*)w)[i];
        uint32_t* d = (uint32_t*)g_wh;
        d[2 * i]     = pack2(v.x, v.y);
        d[2 * i + 1] = pack2(v.z, v.w);
    }
}

// ===========================================================================
// Kernel 1: QKV GEMM (R14 optimum). Block 128x128, 4 warps (2Mx2N), warp
// 64x64. K-chunk 32, 4-stage cp.async, 2 CTAs/SM. A smem [k][m] pitch 272B;
// B smem [n][k] pitch 80B. Per k16 step: 8 LDSM / 32 HMMA (128B/HMMA).
// ===========================================================================
#define K1_ABYTES 8704                 // 32 * 272
#define K1_BBYTES 10240                // 128 * 80
#define K1_STAGE  (K1_ABYTES + K1_BBYTES)
#define K1_SMEM   (4 * K1_STAGE)       // 75776

__global__ __launch_bounds__(128, 2) void k1_qkv_tc(const float* __restrict__ bqkv) {
    extern __shared__ char smc[];
    const uint32_t sb = smem_u32(smc);
    const int t  = threadIdx.x;
    const int o0 = blockIdx.x * 128;
    const int m0 = blockIdx.y * 128;

    const int wid = t >> 5, lane = t & 31;
    const int mw = (wid & 1) * 64;
    const int nw = (wid >> 1) * 64;
    const int grp = lane >> 3, li = lane & 7;
    const int a_k = li + ((grp & 2) ? 8 : 0);
    const int a_m = (grp & 1) ? 8 : 0;
    const int b_n = li + ((grp & 2) ? 8 : 0);
    const int b_k = (grp & 1) ? 8 : 0;
    const int lr = lane >> 2, lq = lane & 3;

    const int a_mh = (t & 15) * 8;
    const int mA   = m0 + a_mh;
    const int nA   = mA / HW;
    const int hwA  = mA - nA * HW;
    const __half* axp = g_xh + (size_t)nA * CHW + hwA;
    const int a_kr0 = t >> 4;            // + 8*i
    const int b_bn0 = t >> 2;            // + 32*i
    const int b_bh  = (t & 3) * 8;

    float c[4][8][4];
#pragma unroll
    for (int mt = 0; mt < 4; mt++)
#pragma unroll
        for (int nt = 0; nt < 8; nt++)
#pragma unroll
            for (int i = 0; i < 4; i++) c[mt][nt][i] = 0.f;

#define K1_ISSUE(kc_) do {                                                    \
    const int s_ = (kc_) & 3;                                                 \
    const uint32_t ab_ = sb + s_ * K1_STAGE;                                  \
    const uint32_t bb_ = ab_ + K1_ABYTES;                                     \
    _Pragma("unroll")                                                         \
    for (int i_ = 0; i_ < 4; i_++) {                                          \
        const int kr_ = a_kr0 + 8 * i_;                                       \
        CP_ASYNC16(ab_ + kr_ * 272 + a_mh * 2,                                \
                   axp + (size_t)((kc_) * 32 + kr_) * HW);                    \
        const int bn_ = b_bn0 + 32 * i_;                                      \
        CP_ASYNC16(bb_ + bn_ * 80 + b_bh * 2,                                 \
                   g_wh + (size_t)(o0 + bn_) * 512 + (kc_) * 32 + b_bh);      \
    }                                                                         \
} while (0)

    K1_ISSUE(0); CP_COMMIT();
    K1_ISSUE(1); CP_COMMIT();
    K1_ISSUE(2); CP_COMMIT();

    for (int kc = 0; kc < 16; kc++) {
        CP_WAIT(2);
        __syncthreads();
        if (kc + 3 < 16) { K1_ISSUE(kc + 3); }
        CP_COMMIT();
        const uint32_t ab = sb + (kc & 3) * K1_STAGE;
        const uint32_t bb = ab + K1_ABYTES;
#pragma unroll
        for (int ks = 0; ks < 2; ks++) {
            uint32_t a[4][4];
#pragma unroll
            for (int mt = 0; mt < 4; mt++)
                LDSM_X4T(a[mt], ab + (ks * 16 + a_k) * 272 + (mw + mt * 16 + a_m) * 2);
            uint32_t b[4][4];
#pragma unroll
            for (int ntp = 0; ntp < 4; ntp++)
                LDSM_X4(b[ntp], bb + (nw + ntp * 16 + b_n) * 80 + (ks * 16 + b_k) * 2);
#pragma unroll
            for (int mt = 0; mt < 4; mt++)
#pragma unroll
                for (int ntp = 0; ntp < 4; ntp++) {
                    mma_f16(c[mt][2 * ntp],     a[mt], b[ntp][0], b[ntp][1]);
                    mma_f16(c[mt][2 * ntp + 1], a[mt], b[ntp][2], b[ntp][3]);
                }
        }
    }

    const bool isq = (o0 < QKC);
#pragma unroll
    for (int mt = 0; mt < 4; mt++) {
#pragma unroll
        for (int half = 0; half < 2; half++) {
            const int row = mw + mt * 16 + lr + half * 8;
            const int m   = m0 + row;
            const int n   = m / HW;
            const int hw  = m - n * HW;
            const int h   = hw / W_IMG;
            const int wp  = hw - h * W_IMG;
            const int p   = (h >> 3) * NWIN + (wp >> 3);
            const int pix = ((h & 7) << 3) + (wp & 7);
            const size_t npix = (size_t)((n * P2 + p) * W2 + pix);
            uint32_t* dsth = isq ? ((uint32_t*)g_qh  + npix * 256 + (o0 >> 1))
                                 : ((uint32_t*)g_kvh + npix * 512 + ((o0 - QKC) >> 1));
#pragma unroll
            for (int nt = 0; nt < 8; nt++) {
                const int col = nw + nt * 8 + lq * 2;
                float vx = c[mt][nt][half * 2 + 0] + bqkv[o0 + col];
                float vy = c[mt][nt][half * 2 + 1] + bqkv[o0 + col + 1];
                dsth[col >> 1] = isq ? pack2(vx * SCALE, vy * SCALE) : pack2(vx, vy);
            }
        }
    }
#undef K1_ISSUE
}

// ===========================================================================
// Kernel 2: window means from fp16 q/kv, fp32 accumulation.
// ===========================================================================
__global__ __launch_bounds__(256) void k2_mean() {
    const int np = blockIdx.x;
    const int c2 = threadIdx.x;
    const uint32_t* qb = (const uint32_t*)g_qh  + (size_t)np * W2 * 256 + c2;
    const uint32_t* kb = (const uint32_t*)g_kvh + (size_t)np * W2 * 512 + c2;
    float sqx = 0.f, sqy = 0.f, skx = 0.f, sky = 0.f;
#pragma unroll 8
    for (int pix = 0; pix < W2; pix++) {
        uint32_t qv = qb[(size_t)pix * 256];
        uint32_t kv = kb[(size_t)pix * 512];
        float2 qf = __half22float2(*reinterpret_cast<__half2*>(&qv));
        float2 kf = __half22float2(*reinterpret_cast<__half2*>(&kv));
        sqx += qf.x; sqy += qf.y;
        skx += kf.x; sky += kf.y;
    }
    *(float2*)(g_qwin + (size_t)np * 512 + 2 * c2) = make_float2(sqx * (1.f/64.f), sqy * (1.f/64.f));
    *(float2*)(g_kwin + (size_t)np * 512 + 2 * c2) = make_float2(skx * (1.f/64.f), sky * (1.f/64.f));
}

// ===========================================================================
// Kernel 3: routing logits + top-4 (warp-parallel argmax). grid 784 x 128.
// ===========================================================================
__global__ __launch_bounds__(128) void k3_route() {
    __shared__ float qs[512];
    __shared__ float lg[P2];
    const int np = blockIdx.x;
    const int n  = np / P2;
    const int t  = threadIdx.x;
    for (int c = t; c < 512; c += 128)
        qs[c] = g_qwin[(size_t)np * 512 + c];
    __syncthreads();
    {
        const int win = (t >> 1) < P2 ? (t >> 1) : (P2 - 1);
        const int hf  = t & 1;
        const float4* kr = (const float4*)(g_kwin + (size_t)(n * P2 + win) * 512) + hf * 64;
        const float*  qh = qs + hf * 256;
        float s = 0.f;
#pragma unroll 8
        for (int c4 = 0; c4 < 64; c4++) {
            float4 k4 = kr[c4];
            s += qh[c4 * 4 + 0] * k4.x + qh[c4 * 4 + 1] * k4.y +
                 qh[c4 * 4 + 2] * k4.z + qh[c4 * 4 + 3] * k4.w;
        }
        s += __shfl_xor_sync(0xffffffffu, s, 1);
        if (hf == 0 && (t >> 1) < P2) lg[win] = s;
    }
    __syncthreads();
    if (t < 32) {
        float v0 = (t < P2)      ? lg[t]      : -1e30f;
        float v1 = (t + 32 < P2) ? lg[t + 32] : -1e30f;
#pragma unroll
        for (int sel = 0; sel < TOPK; sel++) {
            float m; int idx;
            if (v0 >= v1) { m = v0; idx = t; } else { m = v1; idx = t + 32; }
#pragma unroll
            for (int off = 16; off; off >>= 1) {
                float om = __shfl_xor_sync(0xffffffffu, m, off);
                int   oi = __shfl_xor_sync(0xffffffffu, idx, off);
                if (om > m || (om == m && oi < idx)) { m = om; idx = oi; }
            }
            if (t == 0) g_idx[np * TOPK + sel] = idx;
            const int wsel = __shfl_sync(0xffffffffu, idx, 0);
            if (wsel == t)      v0 = -1e30f;
            if (wsel == t + 32) v1 = -1e30f;
        }
    }
}

// ===========================================================================
// Kernel 4: attention, fp16 mma + double-buffered cp.async KV.
// Q fragments hoisted to registers once (tsel==0), reused across windows.
// ===========================================================================
#define K4_TILE 9216                   // 64 * 144
#define K4_SMEM (5 * K4_TILE)

__global__ __launch_bounds__(128) void k4_attn_tc() {
    extern __shared__ char smc[];
    const uint32_t sb = smem_u32(smc);
    const uint32_t Qb = sb;

    const int head = blockIdx.x;
    const int np   = blockIdx.y;
    const int n    = np / P2;
    const int t    = threadIdx.x;
    const int wid  = t >> 5;
    const int lane = t & 31;
    const int mw   = wid * 16;
    const int lr   = lane >> 2;
    const int lq   = lane & 3;
    const int grp  = lane >> 3, li = lane & 7;

    const int q_r   = mw + li + ((grp & 1) ? 8 : 0);
    const int q_k   = (grp & 2) ? 8 : 0;
    const int k_n   = li + ((grp & 2) ? 8 : 0);
    const int k_k   = (grp & 1) ? 8 : 0;
    const int v_key = li + ((grp & 1) ? 8 : 0);
    const int v_d   = (grp & 2) ? 8 : 0;

    int widx[TOPK];
#pragma unroll
    for (int i = 0; i < TOPK; i++) widx[i] = g_idx[np * TOPK + i];

#define K4_KV_ISSUE(ts_) do {                                                   \
    const int s_ = (ts_) & 1;                                                   \
    const uint32_t Kb_ = sb + (1 + 2 * s_) * K4_TILE;                           \
    const uint32_t Vb_ = Kb_ + K4_TILE;                                         \
    const __half* kvsrc_ = g_kvh + (size_t)(n * P2 + widx[ts_]) * 64 * 1024 + head * HD; \
    _Pragma("unroll")                                                           \
    for (int i_ = 0; i_ < 4; i_++) {                                            \
        int cq_ = i_ * 128 + t;                                                 \
        int pix_ = cq_ >> 3, h8_ = (cq_ & 7) * 8;                               \
        CP_ASYNC16(Kb_ + pix_ * 144 + h8_ * 2, kvsrc_ + (size_t)pix_ * 1024 + h8_);       \
        CP_ASYNC16(Vb_ + pix_ * 144 + h8_ * 2, kvsrc_ + (size_t)pix_ * 1024 + 512 + h8_); \
    }                                                                           \
} while (0)

    {
        const __half* qsrc = g_qh + (size_t)np * 64 * 512 + head * HD;
#pragma unroll
        for (int i = 0; i < 4; i++) {
            int cq = i * 128 + t;
            int pix = cq >> 3, h8 = (cq & 7) * 8;
            CP_ASYNC16(Qb + pix * 144 + h8 * 2, qsrc + (size_t)pix * 512 + h8);
        }
        K4_KV_ISSUE(0);
        CP_COMMIT();
        K4_KV_ISSUE(1);
        CP_COMMIT();
    }

    float Of[8][4];
#pragma unroll
    for (int dt = 0; dt < 8; dt++)
#pragma unroll
        for (int i = 0; i < 4; i++) Of[dt][i] = 0.f;
    float mrun0 = -1e30f, mrun1 = -1e30f, lrun0 = 0.f, lrun1 = 0.f;
    uint32_t qa[4][4];                  // Q fragments, loaded once

    for (int tsel = 0; tsel < TOPK; tsel++) {
        CP_WAIT(1);
        __syncthreads();
        if (tsel == 0) {
#pragma unroll
            for (int ks = 0; ks < 4; ks++)
                LDSM_X4(qa[ks], Qb + q_r * 144 + (ks * 16 + q_k) * 2);
        }
        const uint32_t Kb = sb + (1 + 2 * (tsel & 1)) * K4_TILE;
        const uint32_t Vb = Kb + K4_TILE;

        float sf[8][4];
#pragma unroll
        for (int nt = 0; nt < 8; nt++)
#pragma unroll
            for (int i = 0; i < 4; i++) sf[nt][i] = 0.f;
#pragma unroll
        for (int ks = 0; ks < 4; ks++) {
#pragma unroll
            for (int ntp = 0; ntp < 4; ntp++) {
                uint32_t b[4];
                LDSM_X4(b, Kb + (ntp * 16 + k_n) * 144 + (ks * 16 + k_k) * 2);
                mma_f16(sf[2 * ntp],     qa[ks], b[0], b[1]);
                mma_f16(sf[2 * ntp + 1], qa[ks], b[2], b[3]);
            }
        }

        float mx0 = -1e30f, mx1 = -1e30f;
#pragma unroll
        for (int nt = 0; nt < 8; nt++) {
            mx0 = fmaxf(mx0, fmaxf(sf[nt][0], sf[nt][1]));
            mx1 = fmaxf(mx1, fmaxf(sf[nt][2], sf[nt][3]));
        }
        mx0 = fmaxf(mx0, __shfl_xor_sync(0xffffffffu, mx0, 1));
        mx0 = fmaxf(mx0, __shfl_xor_sync(0xffffffffu, mx0, 2));
        mx1 = fmaxf(mx1, __shfl_xor_sync(0xffffffffu, mx1, 1));
        mx1 = fmaxf(mx1, __shfl_xor_sync(0xffffffffu, mx1, 2));
        const float mn0 = fmaxf(mrun0, mx0);
        const float mn1 = fmaxf(mrun1, mx1);
        const float cor0 = __expf(mrun0 - mn0);
        const float cor1 = __expf(mrun1 - mn1);
        float ls0 = 0.f, ls1 = 0.f;
        uint32_t pf0[8], pf1[8];
#pragma unroll
        for (int nt = 0; nt < 8; nt++) {
            __half2 h0 = __floats2half2_rn(__expf(sf[nt][0] - mn0), __expf(sf[nt][1] - mn0));
            __half2 h1 = __floats2half2_rn(__expf(sf[nt][2] - mn1), __expf(sf[nt][3] - mn1));
            float2 f0 = __half22float2(h0);
            float2 f1 = __half22float2(h1);
            ls0 += f0.x + f0.y;
            ls1 += f1.x + f1.y;
            pf0[nt] = *reinterpret_cast<uint32_t*>(&h0);
            pf1[nt] = *reinterpret_cast<uint32_t*>(&h1);
        }
        ls0 += __shfl_xor_sync(0xffffffffu, ls0, 1);
        ls0 += __shfl_xor_sync(0xffffffffu, ls0, 2);
        ls1 += __shfl_xor_sync(0xffffffffu, ls1, 1);
        ls1 += __shfl_xor_sync(0xffffffffu, ls1, 2);
        lrun0 = lrun0 * cor0 + ls0;
        lrun1 = lrun1 * cor1 + ls1;
        mrun0 = mn0; mrun1 = mn1;
#pragma unroll
        for (int dt = 0; dt < 8; dt++) {
            Of[dt][0] *= cor0; Of[dt][1] *= cor0;
            Of[dt][2] *= cor1; Of[dt][3] *= cor1;
        }

#pragma unroll
        for (int ks = 0; ks < 4; ks++) {
            uint32_t a[4] = {pf0[2 * ks], pf1[2 * ks], pf0[2 * ks + 1], pf1[2 * ks + 1]};
#pragma unroll
            for (int dtp = 0; dtp < 4; dtp++) {
                uint32_t b[4];
                LDSM_X4T(b, Vb + (ks * 16 + v_key) * 144 + (dtp * 16 + v_d) * 2);
                mma_f16(Of[2 * dtp],     a, b[0], b[1]);
                mma_f16(Of[2 * dtp + 1], a, b[2], b[3]);
            }
        }

        __syncthreads();
        if (tsel + 2 < TOPK) { K4_KV_ISSUE(tsel + 2); }
        CP_COMMIT();
    }

    const float inv0 = 1.f / lrun0;
    const float inv1 = 1.f / lrun1;
    uint32_t* d0 = (uint32_t*)g_aoh + ((size_t)np * W2 + mw + lr)     * 256 + head * 32;
    uint32_t* d1 = (uint32_t*)g_aoh + ((size_t)np * W2 + mw + lr + 8) * 256 + head * 32;
#pragma unroll
    for (int dt = 0; dt < 8; dt++) {
        d0[dt * 4 + lq] = pack2(Of[dt][0] * inv0, Of[dt][1] * inv0);
        d1[dt * 4 + lq] = pack2(Of[dt][2] * inv1, Of[dt][3] * inv1);
    }
#undef K4_KV_ISSUE
}

// ===========================================================================
// Kernel 5: LePE depthwise 3x3 + attn out, half2 channels, NCHW fp32 output.
// ===========================================================================
__global__ __launch_bounds__(256) void k5_out(const float* __restrict__ wlepe,
                                              const float* __restrict__ blepe,
                                              float* __restrict__ out) {
    __shared__ float2 stage[64][33];   // [pix][c2]
    const int cb = blockIdx.x;
    const int p  = blockIdx.y;
    const int n  = blockIdx.z;
    const int c0 = cb * 64;
    const int t  = threadIdx.x;
    const int c2 = t & 31;
    const int pr = t >> 5;

    const int ce = c0 + 2 * c2;
    float wl0[9], wl1[9];
#pragma unroll
    for (int k = 0; k < 9; k++) {
        wl0[k] = wlepe[ce * 9 + k];
        wl1[k] = wlepe[(ce + 1) * 9 + k];
    }
    const float bias0 = blepe[ce];
    const float bias1 = blepe[ce + 1];

    const int wh0 = (p / NWIN) * 8;
    const int ww0 = (p % NWIN) * 8;

    for (int pg = 0; pg < 8; pg++) {
        int pix = pg * 8 + pr;
        int ih = pix >> 3, iw = pix & 7;
        int h = wh0 + ih, w = ww0 + iw;
        float a0 = bias0, a1 = bias1;
#pragma unroll
        for (int kh = 0; kh < 3; kh++) {
            int hh = h + kh - 1;
            if (hh < 0 || hh >= H_IMG) continue;
#pragma unroll
            for (int kw = 0; kw < 3; kw++) {
                int ww = w + kw - 1;
                if (ww < 0 || ww >= W_IMG) continue;
                int pp   = (hh >> 3) * NWIN + (ww >> 3);
                int ppix = ((hh & 7) << 3) + (ww & 7);
                uint32_t vv = *(const uint32_t*)&g_kvh[
                    ((size_t)(n * P2 + pp) * W2 + ppix) * 1024 + 512 + ce];
                float2 vf = __half22float2(*reinterpret_cast<__half2*>(&vv));
                a0 += vf.x * wl0[kh * 3 + kw];
                a1 += vf.y * wl1[kh * 3 + kw];
            }
        }
        uint32_t av = *(const uint32_t*)&g_aoh[((size_t)(n * P2 + p) * W2 + pix) * 512 + ce];
        float2 af = __half22float2(*reinterpret_cast<__half2*>(&av));
        stage[pix][c2] = make_float2(a0 + af.x, a1 + af.y);
    }
    __syncthreads();

    const int wc = t >> 2;
    const int wx = (t & 3) * 2;
    const int cpair = wc >> 1;
    const int csel  = wc & 1;
    const size_t obase = ((size_t)n * C_DIM + c0 + wc) * HW;
    for (int h = 0; h < 8; h++) {
        float2 s0 = stage[h * 8 + wx][cpair];
        float2 s1 = stage[h * 8 + wx + 1][cpair];
        float2 v = csel ? make_float2(s0.y, s1.y) : make_float2(s0.x, s1.x);
        *(float2*)(out + obase + (size_t)(wh0 + h) * W_IMG + ww0 + wx) = v;
    }
}

// ===========================================================================
extern "C" void kernel_launch(void* const* d_in, const int* in_sizes, int n_in,
                              void* d_out, int out_size) {
    const float* x      = (const float*)d_in[0];
    const float* w_qkv  = (const float*)d_in[1];
    const float* b_qkv  = (const float*)d_in[2];
    const float* w_lepe = (const float*)d_in[3];
    const float* b_lepe = (const float*)d_in[4];
    float* out = (float*)d_out;

    cudaFuncSetAttribute(k1_qkv_tc, cudaFuncAttributeMaxDynamicSharedMemorySize, K1_SMEM);
    cudaFuncSetAttribute(k4_attn_tc, cudaFuncAttributeMaxDynamicSharedMemorySize, K4_SMEM);

    k0_half<<<25088, 256>>>(x, w_qkv);
    k1_qkv_tc<<<dim3(12, 392), 128, K1_SMEM>>>(b_qkv);
    k2_mean<<<784, 256>>>();
    k3_route<<<784, 128>>>();
    k4_attn_tc<<<dim3(HEADS, N_IMG * P2), 128, K4_SMEM>>>();
    k5_out<<<dim3(8, P2, N_IMG), 256>>>(w_lepe, b_lepe, out);
}